// round 4
// baseline (speedup 1.0000x reference)
#include <cuda_runtime.h>
#include <math.h>

#define DIMC 1024
#define PIX  1024   // 32*32 spatial
#define BATCH 8
#define NHEAD 16
#define HDIM 64
#define KCONV (DIMC * 9)

// ---------------- scratch (static __device__, no allocs) ----------------
__device__ float g_Qc[BATCH * DIMC * PIX];
__device__ float g_Kc[BATCH * DIMC * PIX];
__device__ float g_Vc[BATCH * DIMC * PIX];
__device__ float g_AO[BATCH * DIMC * PIX];

// ---------------- packed f32x2 helpers ----------------
__device__ __forceinline__ unsigned long long pack2(float lo, float hi) {
    unsigned long long r;
    asm("mov.b64 %0, {%1, %2};" : "=l"(r) : "f"(lo), "f"(hi));
    return r;
}
__device__ __forceinline__ void unpack2(unsigned long long v, float& lo, float& hi) {
    asm("mov.b64 {%0, %1}, %2;" : "=f"(lo), "=f"(hi) : "l"(v));
}
__device__ __forceinline__ void ffma2(unsigned long long& d, unsigned long long a,
                                      unsigned long long b) {
    asm("fma.rn.f32x2 %0, %1, %2, %0;" : "+l"(d) : "l"(a), "l"(b));
}

// =====================================================================
// Conv 3x3 SAME as implicit GEMM:  Out[b, o, p] = sum_{ci,r,s} W[o,ci,r,s]*X[b,ci,y+r-1,x+s-1] + bias[o]
// A = W viewed [1024, 9216] row-major; B = im2col(X) [9216, 1024]; per-batch GEMM.
// Tiles: BM=BN=128, BK=16, 256 threads, 8x8 per thread (f32x2 packed).
// WHICH selects destination scratch buffer (0->Qc, 1->Kc, 2->Vc).
// =====================================================================
template <int WHICH>
__global__ __launch_bounds__(256, 2)
void conv_kernel(const float* __restrict__ X, const float* __restrict__ W,
                 const float* __restrict__ bias) {
    __shared__ float As[16][132];  // [k][m], padded (132*4 bytes = 16B multiple)
    __shared__ float Bs[16][128];  // [k][n]

    const int b  = blockIdx.z;
    const int m0 = blockIdx.y * 128;
    const int n0 = blockIdx.x * 128;
    const int tid = threadIdx.x;
    const int tx = tid & 15, ty = tid >> 4;

    const float* Xb = X + (size_t)b * DIMC * PIX;

    unsigned long long acc[8][4];
#pragma unroll
    for (int i = 0; i < 8; i++)
#pragma unroll
        for (int j = 0; j < 4; j++) acc[i][j] = 0ull;

    // A-load indices: thread covers (a_m, a_m+64) x float4 at a_k
    const int a_m = tid >> 2;
    const int a_k = (tid & 3) * 4;
    // B-load indices: n fixed per thread, k = (tid>>7) + 2*i
    const int b_n = tid & 127;
    const int b_k = tid >> 7;
    const int p  = n0 + b_n;
    const int y0 = (p >> 5) - 1;   // y + r - 1 with r added later
    const int x0 = (p & 31) - 1;

    for (int k0 = 0; k0 < KCONV; k0 += 16) {
        // ---- load A tile (W), transposed into smem ----
#pragma unroll
        for (int i = 0; i < 2; i++) {
            int m = a_m + i * 64;
            float4 v = *reinterpret_cast<const float4*>(
                &W[(size_t)(m0 + m) * KCONV + k0 + a_k]);
            As[a_k + 0][m] = v.x;
            As[a_k + 1][m] = v.y;
            As[a_k + 2][m] = v.z;
            As[a_k + 3][m] = v.w;
        }
        // ---- load B tile (im2col gather) ----
#pragma unroll
        for (int i = 0; i < 8; i++) {
            int kk = b_k + 2 * i;          // 0..15
            int kg = k0 + kk;
            int ci = kg / 9;
            int rs = kg - ci * 9;
            int r  = rs / 3;
            int s  = rs - r * 3;
            int yy = y0 + r;
            int xx = x0 + s;
            float v = 0.f;
            if ((unsigned)yy < 32u && (unsigned)xx < 32u)
                v = Xb[(size_t)ci * PIX + (yy << 5) + xx];
            Bs[kk][b_n] = v;
        }
        __syncthreads();

        // ---- compute ----
#pragma unroll
        for (int kk = 0; kk < 16; kk++) {
            float4 a0 = *reinterpret_cast<const float4*>(&As[kk][ty * 8]);
            float4 a1 = *reinterpret_cast<const float4*>(&As[kk][ty * 8 + 4]);
            float4 b0 = *reinterpret_cast<const float4*>(&Bs[kk][tx * 8]);
            float4 b1 = *reinterpret_cast<const float4*>(&Bs[kk][tx * 8 + 4]);
            unsigned long long bb[4] = {pack2(b0.x, b0.y), pack2(b0.z, b0.w),
                                        pack2(b1.x, b1.y), pack2(b1.z, b1.w)};
            float av[8] = {a0.x, a0.y, a0.z, a0.w, a1.x, a1.y, a1.z, a1.w};
#pragma unroll
            for (int i = 0; i < 8; i++) {
                unsigned long long aa = pack2(av[i], av[i]);
#pragma unroll
                for (int j = 0; j < 4; j++) ffma2(acc[i][j], aa, bb[j]);
            }
        }
        __syncthreads();
    }

    float* Out = (WHICH == 0) ? g_Qc : (WHICH == 1) ? g_Kc : g_Vc;
#pragma unroll
    for (int i = 0; i < 8; i++) {
        int m = m0 + ty * 8 + i;
        float bv = bias[m];
        float* orow = &Out[((size_t)b * DIMC + m) * PIX + n0 + tx * 8];
#pragma unroll
        for (int j = 0; j < 4; j++) {
            float lo, hi;
            unpack2(acc[i][j], lo, hi);
            orow[j * 2 + 0] = lo + bv;
            orow[j * 2 + 1] = hi + bv;
        }
    }
}

// =====================================================================
// Flash-style attention over channels.
// Q/K/V[t, dd] = conv_out[b, t, h*64 + dd];  T = 1024 tokens, d = 64.
// Grid: (16 t-tiles of 64, 16 heads, 8 batches). Block: 256 threads (16x16).
// Dynamic smem: Qs/Ks/Vs/Ss [64][65] + rowc[64] + rowl[64].
// =====================================================================
#define ATTN_SMEM_FLOATS (4 * 64 * 65 + 128)
#define ATTN_SMEM_BYTES  (ATTN_SMEM_FLOATS * 4)

__global__ void attn_kernel(const int* __restrict__ mask) {
    extern __shared__ float sm[];
    float* Qs   = sm;                 // [64][65]
    float* Ks   = Qs + 64 * 65;
    float* Vs   = Ks + 64 * 65;
    float* Ss   = Vs + 64 * 65;
    float* rowc = Ss + 64 * 65;       // [64]
    float* rowl = rowc + 64;          // [64]

    const int b  = blockIdx.z;
    const int h  = blockIdx.y;
    const int t0 = blockIdx.x * 64;
    const int tid = threadIdx.x;
    const int tx = tid & 15, ty = tid >> 4;

    const float* Qg = g_Qc + (size_t)b * DIMC * PIX + h * HDIM;
    const float* Kg = g_Kc + (size_t)b * DIMC * PIX + h * HDIM;
    const float* Vg = g_Vc + (size_t)b * DIMC * PIX + h * HDIM;

    // load Q tile [64][64]
    {
        int dd = tid & 63;
        int tb = tid >> 6;
#pragma unroll
        for (int i = 0; i < 16; i++) {
            int t = tb + 4 * i;
            Qs[t * 65 + dd] = Qg[(size_t)(t0 + t) * PIX + dd];
        }
    }

    float m_i = -1e30f, l_i = 0.f;  // meaningful for tid < 64
    float o[4][4];
#pragma unroll
    for (int i = 0; i < 4; i++)
#pragma unroll
        for (int j = 0; j < 4; j++) o[i][j] = 0.f;

    for (int s0 = 0; s0 < 1024; s0 += 64) {
        __syncthreads();  // protect Qs on first iter / Ss,Vs reuse on later iters
        // load K, V tiles
        {
            int dd = tid & 63;
            int tb = tid >> 6;
#pragma unroll
            for (int i = 0; i < 16; i++) {
                int t = tb + 4 * i;
                Ks[t * 65 + dd] = Kg[(size_t)(s0 + t) * PIX + dd];
                Vs[t * 65 + dd] = Vg[(size_t)(s0 + t) * PIX + dd];
            }
        }
        __syncthreads();

        // S = Q K^T (each thread: 4x4 at (ty*4, tx*4))
        float sacc[4][4];
#pragma unroll
        for (int i = 0; i < 4; i++)
#pragma unroll
            for (int j = 0; j < 4; j++) sacc[i][j] = 0.f;

        for (int dd = 0; dd < 64; dd++) {
            float a[4], bb[4];
#pragma unroll
            for (int i = 0; i < 4; i++) a[i] = Qs[(ty * 4 + i) * 65 + dd];
#pragma unroll
            for (int j = 0; j < 4; j++) bb[j] = Ks[(tx * 4 + j) * 65 + dd];
#pragma unroll
            for (int i = 0; i < 4; i++)
#pragma unroll
                for (int j = 0; j < 4; j++) sacc[i][j] = fmaf(a[i], bb[j], sacc[i][j]);
        }

        // mask + scale, write S tile
#pragma unroll
        for (int i = 0; i < 4; i++) {
            int tg = t0 + ty * 4 + i;
            const int* mrow = &mask[((size_t)b * 1024 + tg) * 1024 + s0 + tx * 4];
#pragma unroll
            for (int j = 0; j < 4; j++) {
                float sv = mrow[j] ? sacc[i][j] * 0.125f : -1e9f;
                Ss[(ty * 4 + i) * 65 + tx * 4 + j] = sv;
            }
        }
        __syncthreads();

        // online softmax per row (threads 0..63)
        if (tid < 64) {
            float mx = m_i;
            for (int s = 0; s < 64; s++) mx = fmaxf(mx, Ss[tid * 65 + s]);
            float c = __expf(m_i - mx);
            float lsum = 0.f;
            for (int s = 0; s < 64; s++) {
                float pv = __expf(Ss[tid * 65 + s] - mx);
                Ss[tid * 65 + s] = pv;
                lsum += pv;
            }
            l_i = l_i * c + lsum;
            m_i = mx;
            rowc[tid] = c;
            if (s0 == 1024 - 64) rowl[tid] = l_i;
        }
        __syncthreads();

        // O = O * c + P @ V
#pragma unroll
        for (int i = 0; i < 4; i++) {
            float c = rowc[ty * 4 + i];
#pragma unroll
            for (int j = 0; j < 4; j++) o[i][j] *= c;
        }
        for (int ss = 0; ss < 64; ss++) {
            float pr[4], vv[4];
#pragma unroll
            for (int i = 0; i < 4; i++) pr[i] = Ss[(ty * 4 + i) * 65 + ss];
#pragma unroll
            for (int j = 0; j < 4; j++) vv[j] = Vs[ss * 65 + tx * 4 + j];
#pragma unroll
            for (int i = 0; i < 4; i++)
#pragma unroll
                for (int j = 0; j < 4; j++) o[i][j] = fmaf(pr[i], vv[j], o[i][j]);
        }
    }
    __syncthreads();

    // normalize and write AO[b, t, h*64 + dd]
#pragma unroll
    for (int i = 0; i < 4; i++) {
        int tg = t0 + ty * 4 + i;
        float inv = 1.f / rowl[ty * 4 + i];
        float* orow = &g_AO[((size_t)b * DIMC + tg) * PIX + h * HDIM + tx * 4];
#pragma unroll
        for (int j = 0; j < 4; j++) orow[j] = o[i][j] * inv;
    }
}

// =====================================================================
// Output projection: Y[bt, j] = sum_i AO[bt, i] * Wo[j, i] + bo[j]
// NT GEMM, M=8192, N=1024, K=1024. Same tile machinery as conv.
// =====================================================================
__global__ __launch_bounds__(256, 2)
void proj_kernel(const float* __restrict__ Wo, const float* __restrict__ bo,
                 float* __restrict__ Out) {
    __shared__ float As[16][132];
    __shared__ float Ws[16][132];

    const int m0 = blockIdx.y * 128;
    const int n0 = blockIdx.x * 128;
    const int tid = threadIdx.x;
    const int tx = tid & 15, ty = tid >> 4;
    const int a_m = tid >> 2;
    const int a_k = (tid & 3) * 4;

    unsigned long long acc[8][4];
#pragma unroll
    for (int i = 0; i < 8; i++)
#pragma unroll
        for (int j = 0; j < 4; j++) acc[i][j] = 0ull;

    for (int k0 = 0; k0 < 1024; k0 += 16) {
#pragma unroll
        for (int i = 0; i < 2; i++) {
            int r = a_m + i * 64;
            float4 va = *reinterpret_cast<const float4*>(
                &g_AO[(size_t)(m0 + r) * 1024 + k0 + a_k]);
            As[a_k + 0][r] = va.x;
            As[a_k + 1][r] = va.y;
            As[a_k + 2][r] = va.z;
            As[a_k + 3][r] = va.w;
            float4 vw = *reinterpret_cast<const float4*>(
                &Wo[(size_t)(n0 + r) * 1024 + k0 + a_k]);
            Ws[a_k + 0][r] = vw.x;
            Ws[a_k + 1][r] = vw.y;
            Ws[a_k + 2][r] = vw.z;
            Ws[a_k + 3][r] = vw.w;
        }
        __syncthreads();

#pragma unroll
        for (int kk = 0; kk < 16; kk++) {
            float4 a0 = *reinterpret_cast<const float4*>(&As[kk][ty * 8]);
            float4 a1 = *reinterpret_cast<const float4*>(&As[kk][ty * 8 + 4]);
            float4 b0 = *reinterpret_cast<const float4*>(&Ws[kk][tx * 8]);
            float4 b1 = *reinterpret_cast<const float4*>(&Ws[kk][tx * 8 + 4]);
            unsigned long long bb[4] = {pack2(b0.x, b0.y), pack2(b0.z, b0.w),
                                        pack2(b1.x, b1.y), pack2(b1.z, b1.w)};
            float av[8] = {a0.x, a0.y, a0.z, a0.w, a1.x, a1.y, a1.z, a1.w};
#pragma unroll
            for (int i = 0; i < 8; i++) {
                unsigned long long aa = pack2(av[i], av[i]);
#pragma unroll
                for (int j = 0; j < 4; j++) ffma2(acc[i][j], aa, bb[j]);
            }
        }
        __syncthreads();
    }

#pragma unroll
    for (int i = 0; i < 8; i++) {
        int m = m0 + ty * 8 + i;
        float* orow = &Out[(size_t)m * 1024 + n0 + tx * 8];
        const float* brow = &bo[n0 + tx * 8];
#pragma unroll
        for (int j = 0; j < 4; j++) {
            float lo, hi;
            unpack2(acc[i][j], lo, hi);
            orow[j * 2 + 0] = lo + brow[j * 2 + 0];
            orow[j * 2 + 1] = hi + brow[j * 2 + 1];
        }
    }
}

// =====================================================================
extern "C" void kernel_launch(void* const* d_in, const int* in_sizes, int n_in,
                              void* d_out, int out_size) {
    const float* q  = (const float*)d_in[0];
    const float* k  = (const float*)d_in[1];
    const float* v  = (const float*)d_in[2];
    const float* Wq = (const float*)d_in[3];
    const float* bq = (const float*)d_in[4];
    const float* Wk = (const float*)d_in[5];
    const float* bk = (const float*)d_in[6];
    const float* Wv = (const float*)d_in[7];
    const float* bv = (const float*)d_in[8];
    const float* Wo = (const float*)d_in[9];
    const float* bo = (const float*)d_in[10];
    const int*  msk = (const int*)d_in[11];
    float* out = (float*)d_out;

    cudaFuncSetAttribute(attn_kernel, cudaFuncAttributeMaxDynamicSharedMemorySize,
                         ATTN_SMEM_BYTES);

    dim3 cgrid(8, 8, 8);
    conv_kernel<0><<<cgrid, 256>>>(q, Wq, bq);
    conv_kernel<1><<<cgrid, 256>>>(k, Wk, bk);
    conv_kernel<2><<<cgrid, 256>>>(v, Wv, bv);

    attn_kernel<<<dim3(16, 16, 8), 256, ATTN_SMEM_BYTES>>>(msk);

    proj_kernel<<<dim3(8, 64), 256>>>(Wo, bo, out);
}

// round 10
// speedup vs baseline: 2.0924x; 2.0924x over previous
#include <cuda_runtime.h>
#include <cuda_bf16.h>
#include <cstdint>
#include <math.h>

#define DIMC 1024
#define PIX  1024   // 32*32 spatial
#define BATCH 8
#define NHEAD 16
#define HDIM 64
#define KCONV (DIMC * 9)
#define XN (BATCH * DIMC * PIX)   // 8388608 elems per tensor
#define WN (DIMC * KCONV)         // 9437184 elems per weight

// ---------------- scratch (static __device__, no allocs) ----------------
__device__ float g_Qc[XN];
__device__ float g_Kc[XN];
__device__ float g_Vc[XN];
__device__ float g_AO[XN];
__device__ unsigned       g_Xpk[3 * XN];   // packed bf16 (hi | lo<<16) of q,k,v
__device__ unsigned short g_Whi[3 * WN];   // bf16 hi of Wq,Wk,Wv
__device__ unsigned short g_Wlo[3 * WN];   // bf16 lo

// ---------------- packed f32x2 helpers (proj kernel) ----------------
__device__ __forceinline__ unsigned long long pack2(float lo, float hi) {
    unsigned long long r;
    asm("mov.b64 %0, {%1, %2};" : "=l"(r) : "f"(lo), "f"(hi));
    return r;
}
__device__ __forceinline__ void unpack2(unsigned long long v, float& lo, float& hi) {
    asm("mov.b64 {%0, %1}, %2;" : "=f"(lo), "=f"(hi) : "l"(v));
}
__device__ __forceinline__ void ffma2(unsigned long long& d, unsigned long long a,
                                      unsigned long long b) {
    asm("fma.rn.f32x2 %0, %1, %2, %0;" : "+l"(d) : "l"(a), "l"(b));
}

// ---------------- mma.sync / ldmatrix / cp.async helpers (sm_80+ baseline) ----
__device__ __forceinline__ uint32_t smem_u32(const void* p) {
    uint32_t a;
    asm("{ .reg .u64 t; cvta.to.shared.u64 t, %1; cvt.u32.u64 %0, t; }"
        : "=r"(a) : "l"(p));
    return a;
}
__device__ __forceinline__ void mma_bf16(float* c, const unsigned* a, const unsigned* b) {
    asm volatile(
        "mma.sync.aligned.m16n8k16.row.col.f32.bf16.bf16.f32 "
        "{%0,%1,%2,%3}, {%4,%5,%6,%7}, {%8,%9}, {%0,%1,%2,%3};"
        : "+f"(c[0]), "+f"(c[1]), "+f"(c[2]), "+f"(c[3])
        : "r"(a[0]), "r"(a[1]), "r"(a[2]), "r"(a[3]), "r"(b[0]), "r"(b[1]));
}
__device__ __forceinline__ void ldsm_x4(unsigned* r, uint32_t addr) {
    asm volatile("ldmatrix.sync.aligned.m8n8.x4.shared.b16 {%0,%1,%2,%3}, [%4];"
                 : "=r"(r[0]), "=r"(r[1]), "=r"(r[2]), "=r"(r[3]) : "r"(addr));
}
__device__ __forceinline__ void cp_async16(uint32_t dst, const void* src) {
    asm volatile("cp.async.cg.shared.global [%0], [%1], 16;" :: "r"(dst), "l"(src));
}
__device__ __forceinline__ void cp_commit() {
    asm volatile("cp.async.commit_group;" ::: "memory");
}
__device__ __forceinline__ void cp_wait0() {
    asm volatile("cp.async.wait_group 0;" ::: "memory");
}
__device__ __forceinline__ unsigned sw128(unsigned o) {
    return o ^ ((o >> 3) & 0x70);
}

// =====================================================================
// Precision-split pre-pack kernels
// =====================================================================
__global__ void pack_x_kernel(const float* __restrict__ X, int which) {
    unsigned* out = g_Xpk + (size_t)which * XN;
    const float4* X4 = (const float4*)X;
    int stride = gridDim.x * blockDim.x;
    for (int idx = blockIdx.x * blockDim.x + threadIdx.x; idx < XN / 4; idx += stride) {
        float4 x = X4[idx];
        float v[4] = {x.x, x.y, x.z, x.w};
        unsigned r[4];
#pragma unroll
        for (int j = 0; j < 4; j++) {
            __nv_bfloat16 h = __float2bfloat16(v[j]);
            float hf = __bfloat162float(h);
            __nv_bfloat16 l = __float2bfloat16(v[j] - hf);
            r[j] = (unsigned)__bfloat16_as_ushort(h) |
                   ((unsigned)__bfloat16_as_ushort(l) << 16);
        }
        ((uint4*)out)[idx] = make_uint4(r[0], r[1], r[2], r[3]);
    }
}

__global__ void split_w_kernel(const float* __restrict__ W, int which) {
    unsigned short* oh = g_Whi + (size_t)which * WN;
    unsigned short* ol = g_Wlo + (size_t)which * WN;
    const float4* W4 = (const float4*)W;
    int stride = gridDim.x * blockDim.x;
    for (int idx = blockIdx.x * blockDim.x + threadIdx.x; idx < WN / 4; idx += stride) {
        float4 x = W4[idx];
        float v[4] = {x.x, x.y, x.z, x.w};
        unsigned short hs[4], ls[4];
#pragma unroll
        for (int j = 0; j < 4; j++) {
            __nv_bfloat16 h = __float2bfloat16(v[j]);
            float hf = __bfloat162float(h);
            __nv_bfloat16 l = __float2bfloat16(v[j] - hf);
            hs[j] = __bfloat16_as_ushort(h);
            ls[j] = __bfloat16_as_ushort(l);
        }
        uint2 hv = make_uint2((unsigned)hs[0] | ((unsigned)hs[1] << 16),
                              (unsigned)hs[2] | ((unsigned)hs[3] << 16));
        uint2 lv = make_uint2((unsigned)ls[0] | ((unsigned)ls[1] << 16),
                              (unsigned)ls[2] | ((unsigned)ls[3] << 16));
        ((uint2*)oh)[idx] = hv;
        ((uint2*)ol)[idx] = lv;
    }
}

// =====================================================================
// Conv 3x3 SAME as implicit GEMM on mma.sync bf16 (split precision).
// C[m][n] = sum_k W[m][k] * im2col[n][k]  (both K-major -> mma row.col).
// CTA tile 128x128, BK=64, 8 warps (2m x 4n), warp tile 64x32.
// Smem per stage: Ah/Al/Bh/Bl each [128][64] bf16, 128B rows, XOR-128 swizzle.
// Double-buffered (2 x 64KB). A filled by cp.async.cg; B im2col gathered
// through registers (32 words/thread) staged across compute.
// D += Ah*Bh + Ah*Bl + Al*Bh.
// =====================================================================
#define CONV_SMEM_BYTES (2 * 65536)
#define NSTAGE (KCONV / 64)   // 144

__device__ __forceinline__ void load_b_regs(const unsigned* __restrict__ Xb,
                                            int n0, int t, int k0, unsigned* w) {
    int n_local = t >> 1;
    int khalf = t & 1;
    int kg = k0 + khalf * 32;
    int ci = kg / 9;
    int rs = kg - ci * 9;
    int r = rs / 3;
    int s = rs - r * 3;
    int p  = n0 + n_local;
    int py = p >> 5, px = p & 31;
#pragma unroll
    for (int j = 0; j < 32; j++) {
        int yy = py + r - 1, xx = px + s - 1;
        unsigned v = 0;
        if ((unsigned)yy < 32u && (unsigned)xx < 32u)
            v = Xb[(ci << 10) + (yy << 5) + xx];
        w[j] = v;
        if (++s == 3) { s = 0; if (++r == 3) { r = 0; ++ci; } }
    }
}

__device__ __forceinline__ void store_b(char* Bh, char* Bl, int t, const unsigned* w) {
    int n_local = t >> 1, khalf = t & 1;
#pragma unroll
    for (int cg = 0; cg < 4; cg++) {
        unsigned h[4], l[4];
#pragma unroll
        for (int q = 0; q < 4; q++) {
            unsigned w0 = w[cg * 8 + q * 2], w1 = w[cg * 8 + q * 2 + 1];
            h[q] = (w0 & 0xffffu) | (w1 << 16);
            l[q] = (w0 >> 16) | (w1 & 0xffff0000u);
        }
        unsigned o = n_local * 128 + khalf * 64 + cg * 16;
        unsigned sw = sw128(o);
        *(uint4*)(Bh + sw) = make_uint4(h[0], h[1], h[2], h[3]);
        *(uint4*)(Bl + sw) = make_uint4(l[0], l[1], l[2], l[3]);
    }
}

__device__ __forceinline__ void cpasync_a(uint32_t Ah, uint32_t Al,
                                          const unsigned short* __restrict__ Whi,
                                          const unsigned short* __restrict__ Wlo,
                                          int t, int m0, int k0) {
#pragma unroll
    for (int i = 0; i < 4; i++) {
        int idx = t + 256 * i;
        int row = idx >> 3, ch = idx & 7;
        size_t goff = (size_t)(m0 + row) * KCONV + k0 + ch * 8;
        unsigned sw = sw128(row * 128 + ch * 16);
        cp_async16(Ah + sw, Whi + goff);
        cp_async16(Al + sw, Wlo + goff);
    }
}

template <int WHICH>
__global__ __launch_bounds__(256, 1)
void conv_mma_kernel(const float* __restrict__ bias) {
    extern __shared__ char smem[];
    const uint32_t sb = smem_u32(smem);
    const int t = threadIdx.x;
    const int lane = t & 31, wid = t >> 5;
    const int wm = wid & 1, wn = wid >> 1;     // 2m x 4n warp grid
    const int b = blockIdx.z, m0 = blockIdx.y * 128, n0 = blockIdx.x * 128;

    const unsigned short* Whi = g_Whi + (size_t)WHICH * WN;
    const unsigned short* Wlo = g_Wlo + (size_t)WHICH * WN;
    const unsigned* Xb = g_Xpk + (size_t)WHICH * XN + (size_t)b * (DIMC * PIX);

    float c[4][4][4];
#pragma unroll
    for (int i = 0; i < 4; i++)
#pragma unroll
        for (int j = 0; j < 4; j++)
#pragma unroll
            for (int q = 0; q < 4; q++) c[i][j][q] = 0.f;

    unsigned w[32];

    // ---- prologue: stage 0 ----
    load_b_regs(Xb, n0, t, 0, w);
    cpasync_a(sb, sb + 16384, Whi, Wlo, t, m0, 0);
    cp_commit();
    store_b(smem + 32768, smem + 49152, t, w);
    cp_wait0();
    __syncthreads();
    // stage 1 prefetch
    cpasync_a(sb + 65536, sb + 65536 + 16384, Whi, Wlo, t, m0, 64);
    cp_commit();
    load_b_regs(Xb, n0, t, 64, w);

    // lane pieces for ldmatrix addressing
    const int aRow  = lane & 15;
    const int aColH = lane >> 4;
    const int bRow  = (lane & 7) | ((lane >> 4) << 3);
    const int bColH = (lane >> 3) & 1;

    for (int s = 0; s < NSTAGE; s++) {
        const int p = s & 1;
        const uint32_t base = sb + p * 65536;
        const uint32_t Ah = base, Al = base + 16384;
        const uint32_t Bh = base + 32768, Bl = base + 49152;

        // ---- compute: 4 x k16 steps ----
#pragma unroll
        for (int kk = 0; kk < 4; kk++) {
            unsigned ah[4][4], alr[4][4], bh[2][4], blr[2][4];
#pragma unroll
            for (int mb = 0; mb < 4; mb++) {
                unsigned o = (wm * 64 + mb * 16 + aRow) * 128 +
                             (kk * 16 + aColH * 8) * 2;
                unsigned sw = sw128(o);
                ldsm_x4(ah[mb], Ah + sw);
                ldsm_x4(alr[mb], Al + sw);
            }
#pragma unroll
            for (int nb2 = 0; nb2 < 2; nb2++) {
                unsigned o = (wn * 32 + nb2 * 16 + bRow) * 128 +
                             (kk * 16 + bColH * 8) * 2;
                unsigned sw = sw128(o);
                ldsm_x4(bh[nb2], Bh + sw);
                ldsm_x4(blr[nb2], Bl + sw);
            }
#pragma unroll
            for (int mb = 0; mb < 4; mb++)
#pragma unroll
                for (int nb = 0; nb < 4; nb++) {
                    unsigned* fh = &bh[nb >> 1][(nb & 1) * 2];
                    unsigned* fl = &blr[nb >> 1][(nb & 1) * 2];
                    mma_bf16(c[mb][nb], ah[mb], fh);
                    mma_bf16(c[mb][nb], ah[mb], fl);
                    mma_bf16(c[mb][nb], alr[mb], fh);
                }
        }

        if (s + 1 < NSTAGE) {
            // w holds stage s+1 B data; write into the other buffer
            store_b(smem + (p ^ 1) * 65536 + 32768,
                    smem + (p ^ 1) * 65536 + 49152, t, w);
            cp_wait0();   // A(s+1) landed
        }
        __syncthreads();
        if (s + 2 < NSTAGE) {
            cpasync_a(sb + p * 65536, sb + p * 65536 + 16384, Whi, Wlo, t, m0,
                      (s + 2) * 64);
            cp_commit();
            load_b_regs(Xb, n0, t, (s + 2) * 64, w);
        }
    }

    // ---- epilogue ----
    float* Out = (WHICH == 0) ? g_Qc : (WHICH == 1) ? g_Kc : g_Vc;
    const int g = lane >> 2, tg = lane & 3;
#pragma unroll
    for (int mb = 0; mb < 4; mb++) {
        int m = m0 + wm * 64 + mb * 16 + g;
        float bv0 = bias[m];
        float bv1 = bias[m + 8];
#pragma unroll
        for (int nb = 0; nb < 4; nb++) {
            int col = n0 + wn * 32 + nb * 8 + tg * 2;
            float2 v0 = make_float2(c[mb][nb][0] + bv0, c[mb][nb][1] + bv0);
            float2 v1 = make_float2(c[mb][nb][2] + bv1, c[mb][nb][3] + bv1);
            *(float2*)&Out[((size_t)b * DIMC + m) * PIX + col] = v0;
            *(float2*)&Out[((size_t)b * DIMC + m + 8) * PIX + col] = v1;
        }
    }
}

// =====================================================================
// Flash-style attention over channels (fp32 path, unchanged).
// =====================================================================
#define ATTN_SMEM_FLOATS (4 * 64 * 65 + 128)
#define ATTN_SMEM_BYTES  (ATTN_SMEM_FLOATS * 4)

__global__ void attn_kernel(const int* __restrict__ mask) {
    extern __shared__ float sm[];
    float* Qs   = sm;                 // [64][65]
    float* Ks   = Qs + 64 * 65;
    float* Vs   = Ks + 64 * 65;
    float* Ss   = Vs + 64 * 65;
    float* rowc = Ss + 64 * 65;       // [64]
    float* rowl = rowc + 64;          // [64]

    const int b  = blockIdx.z;
    const int h  = blockIdx.y;
    const int t0 = blockIdx.x * 64;
    const int tid = threadIdx.x;
    const int tx = tid & 15, ty = tid >> 4;

    const float* Qg = g_Qc + (size_t)b * DIMC * PIX + h * HDIM;
    const float* Kg = g_Kc + (size_t)b * DIMC * PIX + h * HDIM;
    const float* Vg = g_Vc + (size_t)b * DIMC * PIX + h * HDIM;

    {
        int dd = tid & 63;
        int tb = tid >> 6;
#pragma unroll
        for (int i = 0; i < 16; i++) {
            int t = tb + 4 * i;
            Qs[t * 65 + dd] = Qg[(size_t)(t0 + t) * PIX + dd];
        }
    }

    float m_i = -1e30f, l_i = 0.f;
    float o[4][4];
#pragma unroll
    for (int i = 0; i < 4; i++)
#pragma unroll
        for (int j = 0; j < 4; j++) o[i][j] = 0.f;

    for (int s0 = 0; s0 < 1024; s0 += 64) {
        __syncthreads();
        {
            int dd = tid & 63;
            int tb = tid >> 6;
#pragma unroll
            for (int i = 0; i < 16; i++) {
                int t = tb + 4 * i;
                Ks[t * 65 + dd] = Kg[(size_t)(s0 + t) * PIX + dd];
                Vs[t * 65 + dd] = Vg[(size_t)(s0 + t) * PIX + dd];
            }
        }
        __syncthreads();

        float sacc[4][4];
#pragma unroll
        for (int i = 0; i < 4; i++)
#pragma unroll
            for (int j = 0; j < 4; j++) sacc[i][j] = 0.f;

        for (int dd = 0; dd < 64; dd++) {
            float a[4], bb[4];
#pragma unroll
            for (int i = 0; i < 4; i++) a[i] = Qs[(ty * 4 + i) * 65 + dd];
#pragma unroll
            for (int j = 0; j < 4; j++) bb[j] = Ks[(tx * 4 + j) * 65 + dd];
#pragma unroll
            for (int i = 0; i < 4; i++)
#pragma unroll
                for (int j = 0; j < 4; j++) sacc[i][j] = fmaf(a[i], bb[j], sacc[i][j]);
        }

#pragma unroll
        for (int i = 0; i < 4; i++) {
            int tg = t0 + ty * 4 + i;
            const int* mrow = &mask[((size_t)b * 1024 + tg) * 1024 + s0 + tx * 4];
#pragma unroll
            for (int j = 0; j < 4; j++) {
                float sv = mrow[j] ? sacc[i][j] * 0.125f : -1e9f;
                Ss[(ty * 4 + i) * 65 + tx * 4 + j] = sv;
            }
        }
        __syncthreads();

        if (tid < 64) {
            float mx = m_i;
            for (int s = 0; s < 64; s++) mx = fmaxf(mx, Ss[tid * 65 + s]);
            float cc = __expf(m_i - mx);
            float lsum = 0.f;
            for (int s = 0; s < 64; s++) {
                float pv = __expf(Ss[tid * 65 + s] - mx);
                Ss[tid * 65 + s] = pv;
                lsum += pv;
            }
            l_i = l_i * cc + lsum;
            m_i = mx;
            rowc[tid] = cc;
            if (s0 == 1024 - 64) rowl[tid] = l_i;
        }
        __syncthreads();

#pragma unroll
        for (int i = 0; i < 4; i++) {
            float cc = rowc[ty * 4 + i];
#pragma unroll
            for (int j = 0; j < 4; j++) o[i][j] *= cc;
        }
        for (int ss = 0; ss < 64; ss++) {
            float pr[4], vv[4];
#pragma unroll
            for (int i = 0; i < 4; i++) pr[i] = Ss[(ty * 4 + i) * 65 + ss];
#pragma unroll
            for (int j = 0; j < 4; j++) vv[j] = Vs[ss * 65 + tx * 4 + j];
#pragma unroll
            for (int i = 0; i < 4; i++)
#pragma unroll
                for (int j = 0; j < 4; j++) o[i][j] = fmaf(pr[i], vv[j], o[i][j]);
        }
    }
    __syncthreads();

#pragma unroll
    for (int i = 0; i < 4; i++) {
        int tg = t0 + ty * 4 + i;
        float inv = 1.f / rowl[ty * 4 + i];
        float* orow = &g_AO[((size_t)b * DIMC + tg) * PIX + h * HDIM + tx * 4];
#pragma unroll
        for (int j = 0; j < 4; j++) orow[j] = o[i][j] * inv;
    }
}

// =====================================================================
// Output projection (fp32 f32x2 path, unchanged).
// =====================================================================
__global__ __launch_bounds__(256, 2)
void proj_kernel(const float* __restrict__ Wo, const float* __restrict__ bo,
                 float* __restrict__ Out) {
    __shared__ float As[16][132];
    __shared__ float Ws[16][132];

    const int m0 = blockIdx.y * 128;
    const int n0 = blockIdx.x * 128;
    const int tid = threadIdx.x;
    const int tx = tid & 15, ty = tid >> 4;
    const int a_m = tid >> 2;
    const int a_k = (tid & 3) * 4;

    unsigned long long acc[8][4];
#pragma unroll
    for (int i = 0; i < 8; i++)
#pragma unroll
        for (int j = 0; j < 4; j++) acc[i][j] = 0ull;

    for (int k0 = 0; k0 < 1024; k0 += 16) {
#pragma unroll
        for (int i = 0; i < 2; i++) {
            int r = a_m + i * 64;
            float4 va = *reinterpret_cast<const float4*>(
                &g_AO[(size_t)(m0 + r) * 1024 + k0 + a_k]);
            As[a_k + 0][r] = va.x;
            As[a_k + 1][r] = va.y;
            As[a_k + 2][r] = va.z;
            As[a_k + 3][r] = va.w;
            float4 vw = *reinterpret_cast<const float4*>(
                &Wo[(size_t)(n0 + r) * 1024 + k0 + a_k]);
            Ws[a_k + 0][r] = vw.x;
            Ws[a_k + 1][r] = vw.y;
            Ws[a_k + 2][r] = vw.z;
            Ws[a_k + 3][r] = vw.w;
        }
        __syncthreads();

#pragma unroll
        for (int kk = 0; kk < 16; kk++) {
            float4 a0 = *reinterpret_cast<const float4*>(&As[kk][ty * 8]);
            float4 a1 = *reinterpret_cast<const float4*>(&As[kk][ty * 8 + 4]);
            float4 b0 = *reinterpret_cast<const float4*>(&Ws[kk][tx * 8]);
            float4 b1 = *reinterpret_cast<const float4*>(&Ws[kk][tx * 8 + 4]);
            unsigned long long bb[4] = {pack2(b0.x, b0.y), pack2(b0.z, b0.w),
                                        pack2(b1.x, b1.y), pack2(b1.z, b1.w)};
            float av[8] = {a0.x, a0.y, a0.z, a0.w, a1.x, a1.y, a1.z, a1.w};
#pragma unroll
            for (int i = 0; i < 8; i++) {
                unsigned long long aa = pack2(av[i], av[i]);
#pragma unroll
                for (int j = 0; j < 4; j++) ffma2(acc[i][j], aa, bb[j]);
            }
        }
        __syncthreads();
    }

#pragma unroll
    for (int i = 0; i < 8; i++) {
        int m = m0 + ty * 8 + i;
        float* orow = &Out[(size_t)m * 1024 + n0 + tx * 8];
        const float* brow = &bo[n0 + tx * 8];
#pragma unroll
        for (int j = 0; j < 4; j++) {
            float lo, hi;
            unpack2(acc[i][j], lo, hi);
            orow[j * 2 + 0] = lo + brow[j * 2 + 0];
            orow[j * 2 + 1] = hi + brow[j * 2 + 1];
        }
    }
}

// =====================================================================
extern "C" void kernel_launch(void* const* d_in, const int* in_sizes, int n_in,
                              void* d_out, int out_size) {
    const float* q  = (const float*)d_in[0];
    const float* k  = (const float*)d_in[1];
    const float* v  = (const float*)d_in[2];
    const float* Wq = (const float*)d_in[3];
    const float* bq = (const float*)d_in[4];
    const float* Wk = (const float*)d_in[5];
    const float* bk = (const float*)d_in[6];
    const float* Wv = (const float*)d_in[7];
    const float* bv = (const float*)d_in[8];
    const float* Wo = (const float*)d_in[9];
    const float* bo = (const float*)d_in[10];
    const int*  msk = (const int*)d_in[11];
    float* out = (float*)d_out;

    cudaFuncSetAttribute(attn_kernel, cudaFuncAttributeMaxDynamicSharedMemorySize,
                         ATTN_SMEM_BYTES);
    cudaFuncSetAttribute(conv_mma_kernel<0>,
                         cudaFuncAttributeMaxDynamicSharedMemorySize, CONV_SMEM_BYTES);
    cudaFuncSetAttribute(conv_mma_kernel<1>,
                         cudaFuncAttributeMaxDynamicSharedMemorySize, CONV_SMEM_BYTES);
    cudaFuncSetAttribute(conv_mma_kernel<2>,
                         cudaFuncAttributeMaxDynamicSharedMemorySize, CONV_SMEM_BYTES);

    // precision-split pre-pack
    pack_x_kernel<<<2048, 256>>>(q, 0);
    pack_x_kernel<<<2048, 256>>>(k, 1);
    pack_x_kernel<<<2048, 256>>>(v, 2);
    split_w_kernel<<<2048, 256>>>(Wq, 0);
    split_w_kernel<<<2048, 256>>>(Wk, 1);
    split_w_kernel<<<2048, 256>>>(Wv, 2);

    // convs on mma.sync bf16 tensor cores
    dim3 cgrid(8, 8, 8);
    conv_mma_kernel<0><<<cgrid, 256, CONV_SMEM_BYTES>>>(bq);
    conv_mma_kernel<1><<<cgrid, 256, CONV_SMEM_BYTES>>>(bk);
    conv_mma_kernel<2><<<cgrid, 256, CONV_SMEM_BYTES>>>(bv);

    attn_kernel<<<dim3(16, 16, 8), 256, ATTN_SMEM_BYTES>>>(msk);

    proj_kernel<<<dim3(8, 64), 256>>>(Wo, bo, out);
}